// round 10
// baseline (speedup 1.0000x reference)
#include <cuda_runtime.h>
#include <cuda_bf16.h>
#include <cstdint>

// ============================================================================
// FeedForwardQuantum via mma.sync bf16x3 (hi/lo error compensation).
//   q[m,i]   = cos(x[m,i]) * cos(theta[i]), i<8
//   h[m,f]   = relu(q @ W1^T + b1)   (recomputed per K-tile, split bf16 hi/lo)
//   out[m,e] = h @ W2^T + b2         (3 HMMA passes: hh + h_hi*W_lo + h_lo*W_hi)
// tcgen05 is unavailable (harness PTX targets sm_103 baseline), so this uses
// mma.sync.m16n8k16 + ldmatrix + cp.async, all baseline-PTX legal.
// ============================================================================

namespace {
constexpr int Mtot = 16384, EMB = 1024, FFN = 4096, NQ = 8;
constexpr int BM = 128, BN = 128, BK = 32;
constexpr int NTILE = FFN / BK;     // 128
constexpr int NTH = 256;            // 8 warps, 2x4 warp grid, 64x32 warp tiles
constexpr int RS = 80;              // smem row stride (bytes): 64B data + 16B pad

// per-stage smem offsets (bytes)
constexpr int S_W1  = 0;            // 32*8*4      = 1024
constexpr int S_B1  = 1024;         // 32*4        = 128
constexpr int S_AHI = 1152;         // 128*80      = 10240
constexpr int S_ALO = 11392;
constexpr int S_BHI = 21632;
constexpr int S_BLO = 31872;
constexpr int STAGE = 42112;

constexpr int OFF_Q  = 0;           // 128*8*4 = 4096
constexpr int OFF_ST = 4096;
constexpr int SMEM_BYTES = OFF_ST + 2 * STAGE;   // 88320
}

// W2 pre-split into bf16 hi/lo (device scratch, filled by pre-kernel)
__device__ __nv_bfloat16 g_w2hi[(size_t)EMB * FFN];
__device__ __nv_bfloat16 g_w2lo[(size_t)EMB * FFN];

// ---------------------------------------------------------------------------
__device__ __forceinline__ uint32_t smem_u32(const void* p) {
    uint32_t a;
    asm("{ .reg .u64 t; cvta.to.shared.u64 t, %1; cvt.u32.u64 %0, t; }"
        : "=r"(a) : "l"(p));
    return a;
}
__device__ __forceinline__ void cp16(uint32_t dst, const void* src) {
    asm volatile("cp.async.cg.shared.global [%0], [%1], 16;\n"
                 :: "r"(dst), "l"(src) : "memory");
}
__device__ __forceinline__ void cp_commit() {
    asm volatile("cp.async.commit_group;\n" ::: "memory");
}
__device__ __forceinline__ void cp_wait_all() {
    asm volatile("cp.async.wait_group 0;\n" ::: "memory");
}
__device__ __forceinline__ void ldsm_x4(uint32_t a, uint32_t* r) {
    asm volatile("ldmatrix.sync.aligned.m8n8.x4.shared.b16 {%0,%1,%2,%3}, [%4];\n"
                 : "=r"(r[0]), "=r"(r[1]), "=r"(r[2]), "=r"(r[3]) : "r"(a));
}
__device__ __forceinline__ void mma_bf16(float* c, const uint32_t* a,
                                         const uint32_t* b) {
    asm volatile(
        "mma.sync.aligned.m16n8k16.row.col.f32.bf16.bf16.f32 "
        "{%0,%1,%2,%3}, {%4,%5,%6,%7}, {%8,%9}, {%0,%1,%2,%3};\n"
        : "+f"(c[0]), "+f"(c[1]), "+f"(c[2]), "+f"(c[3])
        : "r"(a[0]), "r"(a[1]), "r"(a[2]), "r"(a[3]), "r"(b[0]), "r"(b[1]));
}

// ---------------------------------------------------------------------------
// pre-kernel: W2 fp32 -> bf16 hi/lo
// ---------------------------------------------------------------------------
__global__ void w2cvt_kernel(const float* __restrict__ w2) {
    size_t i = (size_t)blockIdx.x * blockDim.x + threadIdx.x;  // float4 index
    float4 v = __ldg((const float4*)w2 + i);
    __nv_bfloat162 ph0, ph1, pl0, pl1;
    ph0.x = __float2bfloat16(v.x); ph0.y = __float2bfloat16(v.y);
    ph1.x = __float2bfloat16(v.z); ph1.y = __float2bfloat16(v.w);
    pl0.x = __float2bfloat16(v.x - __bfloat162float(ph0.x));
    pl0.y = __float2bfloat16(v.y - __bfloat162float(ph0.y));
    pl1.x = __float2bfloat16(v.z - __bfloat162float(ph1.x));
    pl1.y = __float2bfloat16(v.w - __bfloat162float(ph1.y));
    ((uint2*)g_w2hi)[i] = make_uint2(*(uint32_t*)&ph0, *(uint32_t*)&ph1);
    ((uint2*)g_w2lo)[i] = make_uint2(*(uint32_t*)&pl0, *(uint32_t*)&pl1);
}

// ---------------------------------------------------------------------------
// main fused kernel
// ---------------------------------------------------------------------------
__global__ __launch_bounds__(NTH, 1)
void ffq_mma_kernel(const float* __restrict__ x, const float* __restrict__ theta,
                    const float* __restrict__ W1, const float* __restrict__ b1,
                    const float* __restrict__ b2, float* __restrict__ out) {
    extern __shared__ char smem[];
    const uint32_t sb = smem_u32(smem);
    const int tid = threadIdx.x, lane = tid & 31, wid = tid >> 5;
    const int wm = wid >> 2, wn = wid & 3;          // 2x4 warp grid
    const int m0 = blockIdx.y * BM, n0 = blockIdx.x * BN;

    // ---- q tile ----
    float* qs = (float*)(smem + OFF_Q);
    for (int e = tid; e < BM * NQ; e += NTH) {
        int m = e >> 3, i = e & 7;
        qs[e] = cosf(__ldg(x + (size_t)(m0 + m) * EMB + i)) *
                cosf(__ldg(theta + i));
    }

    // ---- cp.async stage issue (W2 hi/lo tile + W1 chunk + b1 chunk) ----
    auto issue_stage = [&](int t) {
        const uint32_t st = sb + OFF_ST + (t & 1) * STAGE;
        const int kt = t * BK;
#pragma unroll
        for (int p = 0; p < 2; ++p) {
            int c = tid + p * 256;                  // 0..511
            int row = c >> 2, seg = c & 3;
            size_t gi = (size_t)(n0 + row) * FFN + kt + seg * 8;
            uint32_t so = row * RS + seg * 16;
            cp16(st + S_BHI + so, g_w2hi + gi);
            cp16(st + S_BLO + so, g_w2lo + gi);
        }
        if (tid < 64)
            cp16(st + S_W1 + tid * 16, W1 + (size_t)kt * NQ + tid * 4);
        else if (tid < 72)
            cp16(st + S_B1 + (tid - 64) * 16, b1 + kt + (tid - 64) * 4);
    };

    issue_stage(0);
    cp_commit();
    __syncthreads();                                // qs visible

    // per-thread q registers (h-producer role: row hm, k-half kh)
    const int hm = tid & 127, kh = tid >> 7;
    float ql[8];
#pragma unroll
    for (int i = 0; i < 8; ++i) ql[i] = qs[hm * 8 + i];

    // ldmatrix per-thread address offsets (within a tile)
    uint32_t aoff[4], boff[2];
#pragma unroll
    for (int i = 0; i < 4; ++i)
        aoff[i] = (wm * 64 + i * 16 + (lane & 15)) * RS + (lane >> 4) * 16;
#pragma unroll
    for (int j = 0; j < 2; ++j)
        boff[j] = (wn * 32 + j * 16 + (lane & 7) + ((lane >> 4) & 1) * 8) * RS +
                  ((lane >> 3) & 1) * 16;

    float acc[4][4][4];
#pragma unroll
    for (int i = 0; i < 4; ++i)
#pragma unroll
        for (int j = 0; j < 4; ++j)
#pragma unroll
            for (int r = 0; r < 4; ++r) acc[i][j][r] = 0.0f;

    // ================= main loop =================
    for (int t = 0; t < NTILE; ++t) {
        const int buf = t & 1;
        const uint32_t st = sb + OFF_ST + buf * STAGE;
        char* stp = smem + OFF_ST + buf * STAGE;

        cp_wait_all();                  // stage t data arrived
        __syncthreads();                // S1: + all ldsm of t-1 complete

        if (t + 1 < NTILE) issue_stage(t + 1);   // writes buffer !buf (safe)
        cp_commit();

        // ---- h tile: h = relu(q.W1+b1), split bf16 hi/lo ----
        {
            const float* w1f = (const float*)(stp + S_W1);
            const float* b1f = (const float*)(stp + S_B1);
            uint32_t vh[8], vl[8];
#pragma unroll
            for (int kk = 0; kk < 16; kk += 2) {
                float h2[2];
#pragma unroll
                for (int u = 0; u < 2; ++u) {
                    int k = kh * 16 + kk + u;
                    float4 wa = *(const float4*)(w1f + k * 8);
                    float4 wb = *(const float4*)(w1f + k * 8 + 4);
                    float s = b1f[k];
                    s = fmaf(ql[0], wa.x, s); s = fmaf(ql[1], wa.y, s);
                    s = fmaf(ql[2], wa.z, s); s = fmaf(ql[3], wa.w, s);
                    s = fmaf(ql[4], wb.x, s); s = fmaf(ql[5], wb.y, s);
                    s = fmaf(ql[6], wb.z, s); s = fmaf(ql[7], wb.w, s);
                    h2[u] = fmaxf(s, 0.0f);
                }
                __nv_bfloat162 ph, pl;
                ph.x = __float2bfloat16(h2[0]);
                ph.y = __float2bfloat16(h2[1]);
                pl.x = __float2bfloat16(h2[0] - __bfloat162float(ph.x));
                pl.y = __float2bfloat16(h2[1] - __bfloat162float(ph.y));
                vh[kk >> 1] = *(uint32_t*)&ph;
                vl[kk >> 1] = *(uint32_t*)&pl;
            }
            char* hd = stp + S_AHI + hm * RS + kh * 32;
            char* ld_ = stp + S_ALO + hm * RS + kh * 32;
            *(uint4*)hd        = make_uint4(vh[0], vh[1], vh[2], vh[3]);
            *(uint4*)(hd + 16) = make_uint4(vh[4], vh[5], vh[6], vh[7]);
            *(uint4*)ld_        = make_uint4(vl[0], vl[1], vl[2], vl[3]);
            *(uint4*)(ld_ + 16) = make_uint4(vl[4], vl[5], vl[6], vl[7]);
        }
        __syncthreads();                // S2: h tile visible

        // ---- 3-pass MMA over this K-tile ----
#pragma unroll
        for (int ks = 0; ks < 2; ++ks) {
            uint32_t ahi[4][4], alo[4][4], bhi[4][2], blo[4][2];
#pragma unroll
            for (int i = 0; i < 4; ++i) {
                ldsm_x4(st + S_AHI + aoff[i] + ks * 32, ahi[i]);
                ldsm_x4(st + S_ALO + aoff[i] + ks * 32, alo[i]);
            }
#pragma unroll
            for (int j = 0; j < 2; ++j) {
                uint32_t r[4];
                ldsm_x4(st + S_BHI + boff[j] + ks * 32, r);
                bhi[j * 2][0] = r[0]; bhi[j * 2][1] = r[1];
                bhi[j * 2 + 1][0] = r[2]; bhi[j * 2 + 1][1] = r[3];
                ldsm_x4(st + S_BLO + boff[j] + ks * 32, r);
                blo[j * 2][0] = r[0]; blo[j * 2][1] = r[1];
                blo[j * 2 + 1][0] = r[2]; blo[j * 2 + 1][1] = r[3];
            }
#pragma unroll
            for (int i = 0; i < 4; ++i)
#pragma unroll
                for (int j = 0; j < 4; ++j) {
                    mma_bf16(acc[i][j], ahi[i], bhi[j]);
                    mma_bf16(acc[i][j], ahi[i], blo[j]);
                    mma_bf16(acc[i][j], alo[i], bhi[j]);
                }
        }
    }

    // ================= epilogue: +b2, store =================
#pragma unroll
    for (int i = 0; i < 4; ++i) {
        const int r0 = m0 + wm * 64 + i * 16 + (lane >> 2);
#pragma unroll
        for (int j = 0; j < 4; ++j) {
            const int c0 = n0 + wn * 32 + j * 8 + 2 * (lane & 3);
            float2 bb = *(const float2*)(b2 + c0);
            float2 v0, v1;
            v0.x = acc[i][j][0] + bb.x; v0.y = acc[i][j][1] + bb.y;
            v1.x = acc[i][j][2] + bb.x; v1.y = acc[i][j][3] + bb.y;
            *(float2*)(out + (size_t)r0 * EMB + c0)       = v0;
            *(float2*)(out + (size_t)(r0 + 8) * EMB + c0) = v1;
        }
    }
}

// ---------------------------------------------------------------------------
extern "C" void kernel_launch(void* const* d_in, const int* in_sizes, int n_in,
                              void* d_out, int out_size) {
    const float* x     = (const float*)d_in[0];
    const float* theta = (const float*)d_in[1];
    const float* W1    = (const float*)d_in[2];
    const float* b1    = (const float*)d_in[3];
    const float* W2    = (const float*)d_in[4];
    const float* b2    = (const float*)d_in[5];
    float* out = (float*)d_out;

    cudaFuncSetAttribute(ffq_mma_kernel,
                         cudaFuncAttributeMaxDynamicSharedMemorySize, SMEM_BYTES);

    w2cvt_kernel<<<(EMB * FFN / 4) / 256, 256>>>(W2);

    dim3 grid(EMB / BN, Mtot / BM);   // (8, 128)
    ffq_mma_kernel<<<grid, NTH, SMEM_BYTES>>>(x, theta, W1, b1, b2, out);
}

// round 11
// speedup vs baseline: 1.0000x; 1.0000x over previous
#include <cuda_runtime.h>
#include <cuda_bf16.h>
#include <cstdint>

// ============================================================================
// FeedForwardQuantum via mma.sync bf16x3 (hi/lo error compensation).
//   q[m,i]   = cos(x[m,i]) * cos(theta[i]), i<8
//   h[m,f]   = relu(q @ W1^T + b1)   (recomputed per K-tile, split bf16 hi/lo)
//   out[m,e] = h @ W2^T + b2         (3 HMMA passes: hh + h_hi*W_lo + h_lo*W_hi)
// tcgen05 is unavailable (harness PTX targets sm_103 baseline), so this uses
// mma.sync.m16n8k16 + ldmatrix + cp.async, all baseline-PTX legal.
// ============================================================================

namespace {
constexpr int Mtot = 16384, EMB = 1024, FFN = 4096, NQ = 8;
constexpr int BM = 128, BN = 128, BK = 32;
constexpr int NTILE = FFN / BK;     // 128
constexpr int NTH = 256;            // 8 warps, 2x4 warp grid, 64x32 warp tiles
constexpr int RS = 80;              // smem row stride (bytes): 64B data + 16B pad

// per-stage smem offsets (bytes)
constexpr int S_W1  = 0;            // 32*8*4      = 1024
constexpr int S_B1  = 1024;         // 32*4        = 128
constexpr int S_AHI = 1152;         // 128*80      = 10240
constexpr int S_ALO = 11392;
constexpr int S_BHI = 21632;
constexpr int S_BLO = 31872;
constexpr int STAGE = 42112;

constexpr int OFF_Q  = 0;           // 128*8*4 = 4096
constexpr int OFF_ST = 4096;
constexpr int SMEM_BYTES = OFF_ST + 2 * STAGE;   // 88320
}

// W2 pre-split into bf16 hi/lo (device scratch, filled by pre-kernel)
__device__ __nv_bfloat16 g_w2hi[(size_t)EMB * FFN];
__device__ __nv_bfloat16 g_w2lo[(size_t)EMB * FFN];

// ---------------------------------------------------------------------------
__device__ __forceinline__ uint32_t smem_u32(const void* p) {
    uint32_t a;
    asm("{ .reg .u64 t; cvta.to.shared.u64 t, %1; cvt.u32.u64 %0, t; }"
        : "=r"(a) : "l"(p));
    return a;
}
__device__ __forceinline__ void cp16(uint32_t dst, const void* src) {
    asm volatile("cp.async.cg.shared.global [%0], [%1], 16;\n"
                 :: "r"(dst), "l"(src) : "memory");
}
__device__ __forceinline__ void cp_commit() {
    asm volatile("cp.async.commit_group;\n" ::: "memory");
}
__device__ __forceinline__ void cp_wait_all() {
    asm volatile("cp.async.wait_group 0;\n" ::: "memory");
}
__device__ __forceinline__ void ldsm_x4(uint32_t a, uint32_t* r) {
    asm volatile("ldmatrix.sync.aligned.m8n8.x4.shared.b16 {%0,%1,%2,%3}, [%4];\n"
                 : "=r"(r[0]), "=r"(r[1]), "=r"(r[2]), "=r"(r[3]) : "r"(a));
}
__device__ __forceinline__ void mma_bf16(float* c, const uint32_t* a,
                                         const uint32_t* b) {
    asm volatile(
        "mma.sync.aligned.m16n8k16.row.col.f32.bf16.bf16.f32 "
        "{%0,%1,%2,%3}, {%4,%5,%6,%7}, {%8,%9}, {%0,%1,%2,%3};\n"
        : "+f"(c[0]), "+f"(c[1]), "+f"(c[2]), "+f"(c[3])
        : "r"(a[0]), "r"(a[1]), "r"(a[2]), "r"(a[3]), "r"(b[0]), "r"(b[1]));
}

// ---------------------------------------------------------------------------
// pre-kernel: W2 fp32 -> bf16 hi/lo
// ---------------------------------------------------------------------------
__global__ void w2cvt_kernel(const float* __restrict__ w2) {
    size_t i = (size_t)blockIdx.x * blockDim.x + threadIdx.x;  // float4 index
    float4 v = __ldg((const float4*)w2 + i);
    __nv_bfloat162 ph0, ph1, pl0, pl1;
    ph0.x = __float2bfloat16(v.x); ph0.y = __float2bfloat16(v.y);
    ph1.x = __float2bfloat16(v.z); ph1.y = __float2bfloat16(v.w);
    pl0.x = __float2bfloat16(v.x - __bfloat162float(ph0.x));
    pl0.y = __float2bfloat16(v.y - __bfloat162float(ph0.y));
    pl1.x = __float2bfloat16(v.z - __bfloat162float(ph1.x));
    pl1.y = __float2bfloat16(v.w - __bfloat162float(ph1.y));
    ((uint2*)g_w2hi)[i] = make_uint2(*(uint32_t*)&ph0, *(uint32_t*)&ph1);
    ((uint2*)g_w2lo)[i] = make_uint2(*(uint32_t*)&pl0, *(uint32_t*)&pl1);
}

// ---------------------------------------------------------------------------
// main fused kernel
// ---------------------------------------------------------------------------
__global__ __launch_bounds__(NTH, 1)
void ffq_mma_kernel(const float* __restrict__ x, const float* __restrict__ theta,
                    const float* __restrict__ W1, const float* __restrict__ b1,
                    const float* __restrict__ b2, float* __restrict__ out) {
    extern __shared__ char smem[];
    const uint32_t sb = smem_u32(smem);
    const int tid = threadIdx.x, lane = tid & 31, wid = tid >> 5;
    const int wm = wid >> 2, wn = wid & 3;          // 2x4 warp grid
    const int m0 = blockIdx.y * BM, n0 = blockIdx.x * BN;

    // ---- q tile ----
    float* qs = (float*)(smem + OFF_Q);
    for (int e = tid; e < BM * NQ; e += NTH) {
        int m = e >> 3, i = e & 7;
        qs[e] = cosf(__ldg(x + (size_t)(m0 + m) * EMB + i)) *
                cosf(__ldg(theta + i));
    }

    // ---- cp.async stage issue (W2 hi/lo tile + W1 chunk + b1 chunk) ----
    auto issue_stage = [&](int t) {
        const uint32_t st = sb + OFF_ST + (t & 1) * STAGE;
        const int kt = t * BK;
#pragma unroll
        for (int p = 0; p < 2; ++p) {
            int c = tid + p * 256;                  // 0..511
            int row = c >> 2, seg = c & 3;
            size_t gi = (size_t)(n0 + row) * FFN + kt + seg * 8;
            uint32_t so = row * RS + seg * 16;
            cp16(st + S_BHI + so, g_w2hi + gi);
            cp16(st + S_BLO + so, g_w2lo + gi);
        }
        if (tid < 64)
            cp16(st + S_W1 + tid * 16, W1 + (size_t)kt * NQ + tid * 4);
        else if (tid < 72)
            cp16(st + S_B1 + (tid - 64) * 16, b1 + kt + (tid - 64) * 4);
    };

    issue_stage(0);
    cp_commit();
    __syncthreads();                                // qs visible

    // per-thread q registers (h-producer role: row hm, k-half kh)
    const int hm = tid & 127, kh = tid >> 7;
    float ql[8];
#pragma unroll
    for (int i = 0; i < 8; ++i) ql[i] = qs[hm * 8 + i];

    // ldmatrix per-thread address offsets (within a tile)
    uint32_t aoff[4], boff[2];
#pragma unroll
    for (int i = 0; i < 4; ++i)
        aoff[i] = (wm * 64 + i * 16 + (lane & 15)) * RS + (lane >> 4) * 16;
#pragma unroll
    for (int j = 0; j < 2; ++j)
        boff[j] = (wn * 32 + j * 16 + (lane & 7) + ((lane >> 4) & 1) * 8) * RS +
                  ((lane >> 3) & 1) * 16;

    float acc[4][4][4];
#pragma unroll
    for (int i = 0; i < 4; ++i)
#pragma unroll
        for (int j = 0; j < 4; ++j)
#pragma unroll
            for (int r = 0; r < 4; ++r) acc[i][j][r] = 0.0f;

    // ================= main loop =================
    for (int t = 0; t < NTILE; ++t) {
        const int buf = t & 1;
        const uint32_t st = sb + OFF_ST + buf * STAGE;
        char* stp = smem + OFF_ST + buf * STAGE;

        cp_wait_all();                  // stage t data arrived
        __syncthreads();                // S1: + all ldsm of t-1 complete

        if (t + 1 < NTILE) issue_stage(t + 1);   // writes buffer !buf (safe)
        cp_commit();

        // ---- h tile: h = relu(q.W1+b1), split bf16 hi/lo ----
        {
            const float* w1f = (const float*)(stp + S_W1);
            const float* b1f = (const float*)(stp + S_B1);
            uint32_t vh[8], vl[8];
#pragma unroll
            for (int kk = 0; kk < 16; kk += 2) {
                float h2[2];
#pragma unroll
                for (int u = 0; u < 2; ++u) {
                    int k = kh * 16 + kk + u;
                    float4 wa = *(const float4*)(w1f + k * 8);
                    float4 wb = *(const float4*)(w1f + k * 8 + 4);
                    float s = b1f[k];
                    s = fmaf(ql[0], wa.x, s); s = fmaf(ql[1], wa.y, s);
                    s = fmaf(ql[2], wa.z, s); s = fmaf(ql[3], wa.w, s);
                    s = fmaf(ql[4], wb.x, s); s = fmaf(ql[5], wb.y, s);
                    s = fmaf(ql[6], wb.z, s); s = fmaf(ql[7], wb.w, s);
                    h2[u] = fmaxf(s, 0.0f);
                }
                __nv_bfloat162 ph, pl;
                ph.x = __float2bfloat16(h2[0]);
                ph.y = __float2bfloat16(h2[1]);
                pl.x = __float2bfloat16(h2[0] - __bfloat162float(ph.x));
                pl.y = __float2bfloat16(h2[1] - __bfloat162float(ph.y));
                vh[kk >> 1] = *(uint32_t*)&ph;
                vl[kk >> 1] = *(uint32_t*)&pl;
            }
            char* hd = stp + S_AHI + hm * RS + kh * 32;
            char* ld_ = stp + S_ALO + hm * RS + kh * 32;
            *(uint4*)hd        = make_uint4(vh[0], vh[1], vh[2], vh[3]);
            *(uint4*)(hd + 16) = make_uint4(vh[4], vh[5], vh[6], vh[7]);
            *(uint4*)ld_        = make_uint4(vl[0], vl[1], vl[2], vl[3]);
            *(uint4*)(ld_ + 16) = make_uint4(vl[4], vl[5], vl[6], vl[7]);
        }
        __syncthreads();                // S2: h tile visible

        // ---- 3-pass MMA over this K-tile ----
#pragma unroll
        for (int ks = 0; ks < 2; ++ks) {
            uint32_t ahi[4][4], alo[4][4], bhi[4][2], blo[4][2];
#pragma unroll
            for (int i = 0; i < 4; ++i) {
                ldsm_x4(st + S_AHI + aoff[i] + ks * 32, ahi[i]);
                ldsm_x4(st + S_ALO + aoff[i] + ks * 32, alo[i]);
            }
#pragma unroll
            for (int j = 0; j < 2; ++j) {
                uint32_t r[4];
                ldsm_x4(st + S_BHI + boff[j] + ks * 32, r);
                bhi[j * 2][0] = r[0]; bhi[j * 2][1] = r[1];
                bhi[j * 2 + 1][0] = r[2]; bhi[j * 2 + 1][1] = r[3];
                ldsm_x4(st + S_BLO + boff[j] + ks * 32, r);
                blo[j * 2][0] = r[0]; blo[j * 2][1] = r[1];
                blo[j * 2 + 1][0] = r[2]; blo[j * 2 + 1][1] = r[3];
            }
#pragma unroll
            for (int i = 0; i < 4; ++i)
#pragma unroll
                for (int j = 0; j < 4; ++j) {
                    mma_bf16(acc[i][j], ahi[i], bhi[j]);
                    mma_bf16(acc[i][j], ahi[i], blo[j]);
                    mma_bf16(acc[i][j], alo[i], bhi[j]);
                }
        }
    }

    // ================= epilogue: +b2, store =================
#pragma unroll
    for (int i = 0; i < 4; ++i) {
        const int r0 = m0 + wm * 64 + i * 16 + (lane >> 2);
#pragma unroll
        for (int j = 0; j < 4; ++j) {
            const int c0 = n0 + wn * 32 + j * 8 + 2 * (lane & 3);
            float2 bb = *(const float2*)(b2 + c0);
            float2 v0, v1;
            v0.x = acc[i][j][0] + bb.x; v0.y = acc[i][j][1] + bb.y;
            v1.x = acc[i][j][2] + bb.x; v1.y = acc[i][j][3] + bb.y;
            *(float2*)(out + (size_t)r0 * EMB + c0)       = v0;
            *(float2*)(out + (size_t)(r0 + 8) * EMB + c0) = v1;
        }
    }
}

// ---------------------------------------------------------------------------
extern "C" void kernel_launch(void* const* d_in, const int* in_sizes, int n_in,
                              void* d_out, int out_size) {
    const float* x     = (const float*)d_in[0];
    const float* theta = (const float*)d_in[1];
    const float* W1    = (const float*)d_in[2];
    const float* b1    = (const float*)d_in[3];
    const float* W2    = (const float*)d_in[4];
    const float* b2    = (const float*)d_in[5];
    float* out = (float*)d_out;

    cudaFuncSetAttribute(ffq_mma_kernel,
                         cudaFuncAttributeMaxDynamicSharedMemorySize, SMEM_BYTES);

    w2cvt_kernel<<<(EMB * FFN / 4) / 256, 256>>>(W2);

    dim3 grid(EMB / BN, Mtot / BM);   // (8, 128)
    ffq_mma_kernel<<<grid, NTH, SMEM_BYTES>>>(x, theta, W1, b1, b2, out);
}

// round 13
// speedup vs baseline: 2.1787x; 2.1786x over previous
#include <cuda_runtime.h>
#include <cuda_fp16.h>
#include <cstdint>

// ============================================================================
// FeedForwardQuantum via single-pass fp16 mma.sync (fp32 accumulate).
//   q[m,i]   = cos(x[m,i]) * cos(theta[i]), i<8
//   h[m,f]   = relu(q @ W1^T + b1)   (recomputed per K-tile in fp32, -> fp16)
//   out[m,e] = h @ W2^T + b2         (m16n8k16 f32.f16.f16.f32)
// fp16 unit roundoff 2^-11 -> predicted rel_err ~5-7e-4 < 1e-3 (calibrated
// against measured bf16x3 error == its 2^-16 theory floor).
// 3-buffer cp.async pipeline, 2 CTAs/SM.
// ============================================================================

namespace {
constexpr int Mtot = 16384, EMB = 1024, FFN = 4096, NQ = 8;
constexpr int BM = 128, BN = 128, BK = 32;
constexpr int NTILE = FFN / BK;     // 128
constexpr int NTH = 256;            // 8 warps, 2x4 grid, 64x32 warp tiles
constexpr int RS = 80;              // smem row stride: 64B data + 16B pad

// per-stage smem offsets (bytes)
constexpr int S_W1 = 0;             // 32*8*4 = 1024
constexpr int S_B1 = 1024;          // 128 (pad to 1280)
constexpr int S_A  = 1280;          // 128*80 = 10240 (h, fp16)
constexpr int S_B  = 11520;         // 128*80 = 10240 (W2, fp16)
constexpr int STAGE = 21760;

constexpr int OFF_Q  = 0;           // 128*8*4 = 4096
constexpr int OFF_ST = 4096;
constexpr int NBUF = 3;
constexpr int SMEM_BYTES = OFF_ST + NBUF * STAGE;   // 69376 -> 2 CTAs/SM ok
}

// W2 pre-converted to fp16 (device scratch, filled by pre-kernel)
__device__ __half g_w2h[(size_t)EMB * FFN];

// ---------------------------------------------------------------------------
__device__ __forceinline__ uint32_t smem_u32(const void* p) {
    uint32_t a;
    asm("{ .reg .u64 t; cvta.to.shared.u64 t, %1; cvt.u32.u64 %0, t; }"
        : "=r"(a) : "l"(p));
    return a;
}
__device__ __forceinline__ void cp16(uint32_t dst, const void* src) {
    asm volatile("cp.async.cg.shared.global [%0], [%1], 16;\n"
                 :: "r"(dst), "l"(src) : "memory");
}
__device__ __forceinline__ void cp_commit() {
    asm volatile("cp.async.commit_group;\n" ::: "memory");
}
__device__ __forceinline__ void cp_wait1() {
    asm volatile("cp.async.wait_group 1;\n" ::: "memory");
}
__device__ __forceinline__ void ldsm_x4(uint32_t a, uint32_t* r) {
    asm volatile("ldmatrix.sync.aligned.m8n8.x4.shared.b16 {%0,%1,%2,%3}, [%4];\n"
                 : "=r"(r[0]), "=r"(r[1]), "=r"(r[2]), "=r"(r[3]) : "r"(a));
}
__device__ __forceinline__ void mma_f16(float* c, const uint32_t* a,
                                        const uint32_t* b) {
    asm volatile(
        "mma.sync.aligned.m16n8k16.row.col.f32.f16.f16.f32 "
        "{%0,%1,%2,%3}, {%4,%5,%6,%7}, {%8,%9}, {%0,%1,%2,%3};\n"
        : "+f"(c[0]), "+f"(c[1]), "+f"(c[2]), "+f"(c[3])
        : "r"(a[0]), "r"(a[1]), "r"(a[2]), "r"(a[3]), "r"(b[0]), "r"(b[1]));
}

// ---------------------------------------------------------------------------
// pre-kernel: W2 fp32 -> fp16
// ---------------------------------------------------------------------------
__global__ void w2cvt_kernel(const float* __restrict__ w2) {
    size_t i = (size_t)blockIdx.x * blockDim.x + threadIdx.x;  // float4 index
    float4 v = __ldg((const float4*)w2 + i);
    __half2 a = __floats2half2_rn(v.x, v.y);
    __half2 b = __floats2half2_rn(v.z, v.w);
    ((uint2*)g_w2h)[i] = make_uint2(*(uint32_t*)&a, *(uint32_t*)&b);
}

// ---------------------------------------------------------------------------
// main fused kernel
// ---------------------------------------------------------------------------
__global__ __launch_bounds__(NTH, 2)
void ffq_mma_kernel(const float* __restrict__ x, const float* __restrict__ theta,
                    const float* __restrict__ W1, const float* __restrict__ b1,
                    const float* __restrict__ b2, float* __restrict__ out) {
    extern __shared__ char smem[];
    const uint32_t sb = smem_u32(smem);
    const int tid = threadIdx.x, lane = tid & 31, wid = tid >> 5;
    const int wm = wid >> 2, wn = wid & 3;          // 2x4 warp grid
    const int m0 = blockIdx.y * BM, n0 = blockIdx.x * BN;

    // ---- q tile ----
    float* qs = (float*)(smem + OFF_Q);
    for (int e = tid; e < BM * NQ; e += NTH) {
        int m = e >> 3, i = e & 7;
        qs[e] = cosf(__ldg(x + (size_t)(m0 + m) * EMB + i)) *
                cosf(__ldg(theta + i));
    }

    // ---- cp.async stage issue (W2 fp16 tile + W1 chunk + b1 chunk) ----
    auto issue_stage = [&](int t) {
        const uint32_t st = sb + OFF_ST + (t % NBUF) * STAGE;
        const int kt = t * BK;
#pragma unroll
        for (int p = 0; p < 2; ++p) {
            int c = tid + p * 256;                  // 0..511
            int row = c >> 2, seg = c & 3;
            size_t gi = (size_t)(n0 + row) * FFN + kt + seg * 8;
            cp16(st + S_B + row * RS + seg * 16, g_w2h + gi);
        }
        if (tid < 64)
            cp16(st + S_W1 + tid * 16, W1 + (size_t)kt * NQ + tid * 4);
        else if (tid < 72)
            cp16(st + S_B1 + (tid - 64) * 16, b1 + kt + (tid - 64) * 4);
    };

    issue_stage(0);
    cp_commit();
    issue_stage(1);
    cp_commit();
    __syncthreads();                                // qs visible

    // per-thread q registers (h-producer role: row hm, k-half kh)
    const int hm = tid & 127, kh = tid >> 7;
    float ql[8];
#pragma unroll
    for (int i = 0; i < 8; ++i) ql[i] = qs[hm * 8 + i];

    // ldmatrix per-thread address offsets (within a tile)
    uint32_t aoff[4], boff[2];
#pragma unroll
    for (int i = 0; i < 4; ++i)
        aoff[i] = (wm * 64 + i * 16 + (lane & 15)) * RS + (lane >> 4) * 16;
#pragma unroll
    for (int j = 0; j < 2; ++j)
        boff[j] = (wn * 32 + j * 16 + (lane & 7) + ((lane >> 4) & 1) * 8) * RS +
                  ((lane >> 3) & 1) * 16;

    float acc[4][4][4];
#pragma unroll
    for (int i = 0; i < 4; ++i)
#pragma unroll
        for (int j = 0; j < 4; ++j)
#pragma unroll
            for (int r = 0; r < 4; ++r) acc[i][j][r] = 0.0f;

    // ================= main loop =================
    for (int t = 0; t < NTILE; ++t) {
        const int buf = t % NBUF;
        const uint32_t st = sb + OFF_ST + buf * STAGE;
        char* stp = smem + OFF_ST + buf * STAGE;

        cp_wait1();                     // stage t arrived (<=1 group pending)
        __syncthreads();                // S1: all readers of buf t-? done

        if (t + 2 < NTILE) issue_stage(t + 2);   // buf (t+2)%3 == (t-1)%3: freed
        cp_commit();

        // ---- h tile: h = relu(q.W1+b1) -> fp16 ----
        {
            const float* w1f = (const float*)(stp + S_W1);
            const float* b1f = (const float*)(stp + S_B1);
            uint32_t vh[8];
#pragma unroll
            for (int kk = 0; kk < 16; kk += 2) {
                float h2[2];
#pragma unroll
                for (int u = 0; u < 2; ++u) {
                    int k = kh * 16 + kk + u;
                    float4 wa = *(const float4*)(w1f + k * 8);
                    float4 wb = *(const float4*)(w1f + k * 8 + 4);
                    float s = b1f[k];
                    s = fmaf(ql[0], wa.x, s); s = fmaf(ql[1], wa.y, s);
                    s = fmaf(ql[2], wa.z, s); s = fmaf(ql[3], wa.w, s);
                    s = fmaf(ql[4], wb.x, s); s = fmaf(ql[5], wb.y, s);
                    s = fmaf(ql[6], wb.z, s); s = fmaf(ql[7], wb.w, s);
                    h2[u] = fmaxf(s, 0.0f);
                }
                __half2 ph = __floats2half2_rn(h2[0], h2[1]);
                vh[kk >> 1] = *(uint32_t*)&ph;
            }
            char* hd = stp + S_A + hm * RS + kh * 32;
            *(uint4*)hd        = make_uint4(vh[0], vh[1], vh[2], vh[3]);
            *(uint4*)(hd + 16) = make_uint4(vh[4], vh[5], vh[6], vh[7]);
        }
        __syncthreads();                // S2: h tile visible

        // ---- single-pass MMA over this K-tile ----
#pragma unroll
        for (int ks = 0; ks < 2; ++ks) {
            uint32_t a[4][4], b[4][2];
#pragma unroll
            for (int i = 0; i < 4; ++i)
                ldsm_x4(st + S_A + aoff[i] + ks * 32, a[i]);
#pragma unroll
            for (int j = 0; j < 2; ++j) {
                uint32_t r[4];
                ldsm_x4(st + S_B + boff[j] + ks * 32, r);
                b[j * 2][0] = r[0]; b[j * 2][1] = r[1];
                b[j * 2 + 1][0] = r[2]; b[j * 2 + 1][1] = r[3];
            }
#pragma unroll
            for (int i = 0; i < 4; ++i)
#pragma unroll
                for (int j = 0; j < 4; ++j)
                    mma_f16(acc[i][j], a[i], b[j]);
        }
    }

    // ================= epilogue: +b2, store =================
#pragma unroll
    for (int i = 0; i < 4; ++i) {
        const int r0 = m0 + wm * 64 + i * 16 + (lane >> 2);
#pragma unroll
        for (int j = 0; j < 4; ++j) {
            const int c0 = n0 + wn * 32 + j * 8 + 2 * (lane & 3);
            float2 bb = *(const float2*)(b2 + c0);
            float2 v0, v1;
            v0.x = acc[i][j][0] + bb.x; v0.y = acc[i][j][1] + bb.y;
            v1.x = acc[i][j][2] + bb.x; v1.y = acc[i][j][3] + bb.y;
            *(float2*)(out + (size_t)r0 * EMB + c0)       = v0;
            *(float2*)(out + (size_t)(r0 + 8) * EMB + c0) = v1;
        }
    }
}

// ---------------------------------------------------------------------------
extern "C" void kernel_launch(void* const* d_in, const int* in_sizes, int n_in,
                              void* d_out, int out_size) {
    const float* x     = (const float*)d_in[0];
    const float* theta = (const float*)d_in[1];
    const float* W1    = (const float*)d_in[2];
    const float* b1    = (const float*)d_in[3];
    const float* W2    = (const float*)d_in[4];
    const float* b2    = (const float*)d_in[5];
    float* out = (float*)d_out;

    cudaFuncSetAttribute(ffq_mma_kernel,
                         cudaFuncAttributeMaxDynamicSharedMemorySize, SMEM_BYTES);

    w2cvt_kernel<<<(EMB * FFN / 4) / 256, 256>>>(W2);

    dim3 grid(EMB / BN, Mtot / BM);   // (8, 128)
    ffq_mma_kernel<<<grid, NTH, SMEM_BYTES>>>(x, theta, W1, b1, b2, out);
}

// round 15
// speedup vs baseline: 2.1815x; 1.0013x over previous
#include <cuda_runtime.h>
#include <cuda_fp16.h>
#include <cstdint>

// ============================================================================
// FeedForwardQuantum via single-pass fp16 mma.sync (fp32 accumulate).
//   q[m,i]   = cos(x[m,i]) * cos(theta[i]), i<8
//   h[m,f]   = relu(q @ W1^T + b1)   (recomputed per K-tile in fp32, -> fp16)
//   out[m,e] = h @ W2^T + b2         (m16n8k16 f32.f16.f16.f32)
// fp16 unit roundoff 2^-11 -> predicted rel_err ~5-7e-4 < 1e-3 (calibrated
// against measured bf16x3 error == its 2^-16 theory floor).
// 3-buffer cp.async pipeline, 2 CTAs/SM.
// ============================================================================

namespace {
constexpr int Mtot = 16384, EMB = 1024, FFN = 4096, NQ = 8;
constexpr int BM = 128, BN = 128, BK = 32;
constexpr int NTILE = FFN / BK;     // 128
constexpr int NTH = 256;            // 8 warps, 2x4 grid, 64x32 warp tiles
constexpr int RS = 80;              // smem row stride: 64B data + 16B pad

// per-stage smem offsets (bytes)
constexpr int S_W1 = 0;             // 32*8*4 = 1024
constexpr int S_B1 = 1024;          // 128 (pad to 1280)
constexpr int S_A  = 1280;          // 128*80 = 10240 (h, fp16)
constexpr int S_B  = 11520;         // 128*80 = 10240 (W2, fp16)
constexpr int STAGE = 21760;

constexpr int OFF_Q  = 0;           // 128*8*4 = 4096
constexpr int OFF_ST = 4096;
constexpr int NBUF = 3;
constexpr int SMEM_BYTES = OFF_ST + NBUF * STAGE;   // 69376 -> 2 CTAs/SM ok
}

// W2 pre-converted to fp16 (device scratch, filled by pre-kernel)
__device__ __half g_w2h[(size_t)EMB * FFN];

// ---------------------------------------------------------------------------
__device__ __forceinline__ uint32_t smem_u32(const void* p) {
    uint32_t a;
    asm("{ .reg .u64 t; cvta.to.shared.u64 t, %1; cvt.u32.u64 %0, t; }"
        : "=r"(a) : "l"(p));
    return a;
}
__device__ __forceinline__ void cp16(uint32_t dst, const void* src) {
    asm volatile("cp.async.cg.shared.global [%0], [%1], 16;\n"
                 :: "r"(dst), "l"(src) : "memory");
}
__device__ __forceinline__ void cp_commit() {
    asm volatile("cp.async.commit_group;\n" ::: "memory");
}
__device__ __forceinline__ void cp_wait1() {
    asm volatile("cp.async.wait_group 1;\n" ::: "memory");
}
__device__ __forceinline__ void ldsm_x4(uint32_t a, uint32_t* r) {
    asm volatile("ldmatrix.sync.aligned.m8n8.x4.shared.b16 {%0,%1,%2,%3}, [%4];\n"
                 : "=r"(r[0]), "=r"(r[1]), "=r"(r[2]), "=r"(r[3]) : "r"(a));
}
__device__ __forceinline__ void mma_f16(float* c, const uint32_t* a,
                                        const uint32_t* b) {
    asm volatile(
        "mma.sync.aligned.m16n8k16.row.col.f32.f16.f16.f32 "
        "{%0,%1,%2,%3}, {%4,%5,%6,%7}, {%8,%9}, {%0,%1,%2,%3};\n"
        : "+f"(c[0]), "+f"(c[1]), "+f"(c[2]), "+f"(c[3])
        : "r"(a[0]), "r"(a[1]), "r"(a[2]), "r"(a[3]), "r"(b[0]), "r"(b[1]));
}

// ---------------------------------------------------------------------------
// pre-kernel: W2 fp32 -> fp16
// ---------------------------------------------------------------------------
__global__ void w2cvt_kernel(const float* __restrict__ w2) {
    size_t i = (size_t)blockIdx.x * blockDim.x + threadIdx.x;  // float4 index
    float4 v = __ldg((const float4*)w2 + i);
    __half2 a = __floats2half2_rn(v.x, v.y);
    __half2 b = __floats2half2_rn(v.z, v.w);
    ((uint2*)g_w2h)[i] = make_uint2(*(uint32_t*)&a, *(uint32_t*)&b);
}

// ---------------------------------------------------------------------------
// main fused kernel
// ---------------------------------------------------------------------------
__global__ __launch_bounds__(NTH, 2)
void ffq_mma_kernel(const float* __restrict__ x, const float* __restrict__ theta,
                    const float* __restrict__ W1, const float* __restrict__ b1,
                    const float* __restrict__ b2, float* __restrict__ out) {
    extern __shared__ char smem[];
    const uint32_t sb = smem_u32(smem);
    const int tid = threadIdx.x, lane = tid & 31, wid = tid >> 5;
    const int wm = wid >> 2, wn = wid & 3;          // 2x4 warp grid
    const int m0 = blockIdx.y * BM, n0 = blockIdx.x * BN;

    // ---- q tile ----
    float* qs = (float*)(smem + OFF_Q);
    for (int e = tid; e < BM * NQ; e += NTH) {
        int m = e >> 3, i = e & 7;
        qs[e] = cosf(__ldg(x + (size_t)(m0 + m) * EMB + i)) *
                cosf(__ldg(theta + i));
    }

    // ---- cp.async stage issue (W2 fp16 tile + W1 chunk + b1 chunk) ----
    auto issue_stage = [&](int t) {
        const uint32_t st = sb + OFF_ST + (t % NBUF) * STAGE;
        const int kt = t * BK;
#pragma unroll
        for (int p = 0; p < 2; ++p) {
            int c = tid + p * 256;                  // 0..511
            int row = c >> 2, seg = c & 3;
            size_t gi = (size_t)(n0 + row) * FFN + kt + seg * 8;
            cp16(st + S_B + row * RS + seg * 16, g_w2h + gi);
        }
        if (tid < 64)
            cp16(st + S_W1 + tid * 16, W1 + (size_t)kt * NQ + tid * 4);
        else if (tid < 72)
            cp16(st + S_B1 + (tid - 64) * 16, b1 + kt + (tid - 64) * 4);
    };

    issue_stage(0);
    cp_commit();
    issue_stage(1);
    cp_commit();
    __syncthreads();                                // qs visible

    // per-thread q registers (h-producer role: row hm, k-half kh)
    const int hm = tid & 127, kh = tid >> 7;
    float ql[8];
#pragma unroll
    for (int i = 0; i < 8; ++i) ql[i] = qs[hm * 8 + i];

    // ldmatrix per-thread address offsets (within a tile)
    uint32_t aoff[4], boff[2];
#pragma unroll
    for (int i = 0; i < 4; ++i)
        aoff[i] = (wm * 64 + i * 16 + (lane & 15)) * RS + (lane >> 4) * 16;
#pragma unroll
    for (int j = 0; j < 2; ++j)
        boff[j] = (wn * 32 + j * 16 + (lane & 7) + ((lane >> 4) & 1) * 8) * RS +
                  ((lane >> 3) & 1) * 16;

    float acc[4][4][4];
#pragma unroll
    for (int i = 0; i < 4; ++i)
#pragma unroll
        for (int j = 0; j < 4; ++j)
#pragma unroll
            for (int r = 0; r < 4; ++r) acc[i][j][r] = 0.0f;

    // ================= main loop =================
    for (int t = 0; t < NTILE; ++t) {
        const int buf = t % NBUF;
        const uint32_t st = sb + OFF_ST + buf * STAGE;
        char* stp = smem + OFF_ST + buf * STAGE;

        cp_wait1();                     // stage t arrived (<=1 group pending)
        __syncthreads();                // S1: all readers of buf t-? done

        if (t + 2 < NTILE) issue_stage(t + 2);   // buf (t+2)%3 == (t-1)%3: freed
        cp_commit();

        // ---- h tile: h = relu(q.W1+b1) -> fp16 ----
        {
            const float* w1f = (const float*)(stp + S_W1);
            const float* b1f = (const float*)(stp + S_B1);
            uint32_t vh[8];
#pragma unroll
            for (int kk = 0; kk < 16; kk += 2) {
                float h2[2];
#pragma unroll
                for (int u = 0; u < 2; ++u) {
                    int k = kh * 16 + kk + u;
                    float4 wa = *(const float4*)(w1f + k * 8);
                    float4 wb = *(const float4*)(w1f + k * 8 + 4);
                    float s = b1f[k];
                    s = fmaf(ql[0], wa.x, s); s = fmaf(ql[1], wa.y, s);
                    s = fmaf(ql[2], wa.z, s); s = fmaf(ql[3], wa.w, s);
                    s = fmaf(ql[4], wb.x, s); s = fmaf(ql[5], wb.y, s);
                    s = fmaf(ql[6], wb.z, s); s = fmaf(ql[7], wb.w, s);
                    h2[u] = fmaxf(s, 0.0f);
                }
                __half2 ph = __floats2half2_rn(h2[0], h2[1]);
                vh[kk >> 1] = *(uint32_t*)&ph;
            }
            char* hd = stp + S_A + hm * RS + kh * 32;
            *(uint4*)hd        = make_uint4(vh[0], vh[1], vh[2], vh[3]);
            *(uint4*)(hd + 16) = make_uint4(vh[4], vh[5], vh[6], vh[7]);
        }
        __syncthreads();                // S2: h tile visible

        // ---- single-pass MMA over this K-tile ----
#pragma unroll
        for (int ks = 0; ks < 2; ++ks) {
            uint32_t a[4][4], b[4][2];
#pragma unroll
            for (int i = 0; i < 4; ++i)
                ldsm_x4(st + S_A + aoff[i] + ks * 32, a[i]);
#pragma unroll
            for (int j = 0; j < 2; ++j) {
                uint32_t r[4];
                ldsm_x4(st + S_B + boff[j] + ks * 32, r);
                b[j * 2][0] = r[0]; b[j * 2][1] = r[1];
                b[j * 2 + 1][0] = r[2]; b[j * 2 + 1][1] = r[3];
            }
#pragma unroll
            for (int i = 0; i < 4; ++i)
#pragma unroll
                for (int j = 0; j < 4; ++j)
                    mma_f16(acc[i][j], a[i], b[j]);
        }
    }

    // ================= epilogue: +b2, store =================
#pragma unroll
    for (int i = 0; i < 4; ++i) {
        const int r0 = m0 + wm * 64 + i * 16 + (lane >> 2);
#pragma unroll
        for (int j = 0; j < 4; ++j) {
            const int c0 = n0 + wn * 32 + j * 8 + 2 * (lane & 3);
            float2 bb = *(const float2*)(b2 + c0);
            float2 v0, v1;
            v0.x = acc[i][j][0] + bb.x; v0.y = acc[i][j][1] + bb.y;
            v1.x = acc[i][j][2] + bb.x; v1.y = acc[i][j][3] + bb.y;
            *(float2*)(out + (size_t)r0 * EMB + c0)       = v0;
            *(float2*)(out + (size_t)(r0 + 8) * EMB + c0) = v1;
        }
    }
}

// ---------------------------------------------------------------------------
extern "C" void kernel_launch(void* const* d_in, const int* in_sizes, int n_in,
                              void* d_out, int out_size) {
    const float* x     = (const float*)d_in[0];
    const float* theta = (const float*)d_in[1];
    const float* W1    = (const float*)d_in[2];
    const float* b1    = (const float*)d_in[3];
    const float* W2    = (const float*)d_in[4];
    const float* b2    = (const float*)d_in[5];
    float* out = (float*)d_out;

    cudaFuncSetAttribute(ffq_mma_kernel,
                         cudaFuncAttributeMaxDynamicSharedMemorySize, SMEM_BYTES);

    w2cvt_kernel<<<(EMB * FFN / 4) / 256, 256>>>(W2);

    dim3 grid(EMB / BN, Mtot / BM);   // (8, 128)
    ffq_mma_kernel<<<grid, NTH, SMEM_BYTES>>>(x, theta, W1, b1, b2, out);
}